// round 14
// baseline (speedup 1.0000x reference)
#include <cuda_runtime.h>
#include <cstdint>

#define Bb   2
#define Tt   2048
#define Dd   1024
#define Hh   16
#define HDIM 64
#define MTOT (Bb*Tt)        // 4096
#define NITEMS 512          // flash work items (16 qt x 16 h x 2 b)

// Scratch (allocation-free rule: __device__ globals)
__device__ float g_q[Bb*Hh*Tt*HDIM];     // d-dim permuted
__device__ float g_k[Bb*Hh*Tt*HDIM];     // d-dim permuted
__device__ float g_vt[Bb*Hh*HDIM*Tt];    // transposed V [b][h][d][tperm]
__device__ float g_ctx[Bb*Tt*Dd];        // d-dim permuted (A of Wo gemm)
__device__ float g_xr[MTOT*Dd];          // tf32-rounded x, k-perm
__device__ float g_wt[4][Dd*Dd];         // tf32-rounded W^T [n][k], k-perm
__device__ int   g_ctr;                  // flash work counter

// ---- helpers --------------------------------------------------------------
__device__ __forceinline__ unsigned rtf_u(float x) {
    unsigned u; asm("cvt.rna.tf32.f32 %0, %1;" : "=r"(u) : "f"(x)); return u;
}
__device__ __forceinline__ float rtf(float x) { return __uint_as_float(rtf_u(x)); }
__device__ __forceinline__ unsigned f2u(float x) { return __float_as_uint(x); }
__device__ __forceinline__ void cpa16(void* dst, const void* src) {
    unsigned s = (unsigned)__cvta_generic_to_shared(dst);
    asm volatile("cp.async.cg.shared.global [%0], [%1], 16;\n" :: "r"(s), "l"(src));
}
__device__ __forceinline__ float ex2(float x) {
    float y; asm("ex2.approx.ftz.f32 %0, %1;" : "=f"(y) : "f"(x)); return y;
}
// position p holds original k-offset (p>>1)+4*(p&1)  (within each 8-block)
__device__ __forceinline__ int korig(int p) {
    return (p & ~7) + (((p & 7) >> 1)) + 4 * (p & 1);
}
// original offset c stored at position 2*(c&3)+((c>>2)&1)
__device__ __forceinline__ int kpos(int c) {
    return (c & ~7) + 2 * (c & 3) + ((c >> 2) & 1);
}
// mma.sync m16n8k8 tf32: D += A*B
__device__ __forceinline__ void mma8(float* d, const unsigned* a, const unsigned* b) {
    asm volatile(
        "mma.sync.aligned.m16n8k8.row.col.f32.tf32.tf32.f32 "
        "{%0,%1,%2,%3}, {%4,%5,%6,%7}, {%8,%9}, {%0,%1,%2,%3};\n"
        : "+f"(d[0]), "+f"(d[1]), "+f"(d[2]), "+f"(d[3])
        : "r"(a[0]), "r"(a[1]), "r"(a[2]), "r"(a[3]), "r"(b[0]), "r"(b[1]));
}

// ---------------------------------------------------------------------------
// preround_x: g_xr[m][p] = rtf(x[m][korig(p)]);  also resets flash counter.
// ---------------------------------------------------------------------------
__global__ void preround_x(const float* __restrict__ x) {
    if (blockIdx.x == 0 && threadIdx.x == 0) g_ctr = 0;
    int i = (blockIdx.x * 256 + threadIdx.x) * 4;
    int m = i >> 10, kp = i & 1023;
    const float* row = x + (size_t)m * 1024;
    float4 o;
    o.x = rtf(row[korig(kp)]);
    o.y = rtf(row[korig(kp + 1)]);
    o.z = rtf(row[korig(kp + 2)]);
    o.w = rtf(row[korig(kp + 3)]);
    *(float4*)&g_xr[i] = o;
}

// ---------------------------------------------------------------------------
// transW: g_wt[z][n][p] = rtf(W_z[k0+korig(p)][n])  (transpose + k-perm)
// ---------------------------------------------------------------------------
__global__ void transW(const float* __restrict__ wq, const float* __restrict__ wk,
                       const float* __restrict__ wv, const float* __restrict__ wo)
{
    __shared__ float t[32][33];
    int z = blockIdx.z;
    const float* W = (z == 0) ? wq : (z == 1) ? wk : (z == 2) ? wv : wo;
    float* D = g_wt[z];
    int k0 = blockIdx.x * 32, n0 = blockIdx.y * 32;
    int tx = threadIdx.x, ty = threadIdx.y;
    #pragma unroll
    for (int i = 0; i < 32; i += 8)
        t[ty + i][tx] = rtf(W[(size_t)(k0 + ty + i) * 1024 + n0 + tx]);
    __syncthreads();
    int src = korig(tx);
    #pragma unroll
    for (int i = 0; i < 32; i += 8)
        D[(size_t)(n0 + ty + i) * 1024 + k0 + tx] = t[src][ty + i];
}

// ---------------------------------------------------------------------------
// GEMM (tf32 mma.sync, 3-stage cp.async, 512 threads, 256x128 CTA tile):
// 16 warps (4m x 4n), warp tile 64x32.  wait_group 1 -> 2-iteration latency
// cover.  A,Wt k-permuted -> frag pairs adjacent -> LDS.64.  Strides 40.
// mode 0: row-major + bias.
// mode 1: z∈{0,1} -> Q/K head-split d-permuted; z==2 -> V transposed+key-perm.
// ---------------------------------------------------------------------------
#define AS_ST (256*40)
#define WS_ST (128*40)
#define GSTG  3
#define GSMEM (GSTG * (AS_ST + WS_ST) * 4)     // 184320 B

__global__ __launch_bounds__(512, 1)
void gemm_mma(const float* __restrict__ A,
              const float* __restrict__ W0, const float* __restrict__ W1,
              const float* __restrict__ W2,
              float* __restrict__ C0, float* __restrict__ C1,
              float* __restrict__ C2,
              const float* __restrict__ bias, int mode)
{
    extern __shared__ float sh[];
    float* Apool = sh;                  // [3][256][40]
    float* Wpool = sh + GSTG * AS_ST;   // [3][128][40]  ([n][k] layout)

    const float* W = (blockIdx.z == 0) ? W0 : (blockIdx.z == 1) ? W1 : W2;
    float*       C = (blockIdx.z == 0) ? C0 : (blockIdx.z == 1) ? C1 : C2;

    const int tid = threadIdx.x;
    const int lane = tid & 31, warp = tid >> 5;
    const int g = lane >> 2, tg = lane & 3;
    const int wm = warp >> 2;       // 0..3  (64 rows each)
    const int wn = warp & 3;        // 0..3  (32 cols each)
    const int m0 = blockIdx.y * 256;
    const int n0 = blockIdx.x * 128;

    float acc[4][4][4];
    #pragma unroll
    for (int mt = 0; mt < 4; mt++)
        #pragma unroll
        for (int nt = 0; nt < 4; nt++)
            #pragma unroll
            for (int c = 0; c < 4; c++) acc[mt][nt][c] = 0.f;

    auto ISSUE = [&](int it) {
        const int k0 = it * 32;
        float* Ab = Apool + (it % GSTG) * AS_ST;
        float* Wb = Wpool + (it % GSTG) * WS_ST;
        #pragma unroll
        for (int j = 0; j < 4; j++) {          // A: 256 rows x 32 floats
            int id = j * 512 + tid;
            int r = id >> 3, c = id & 7;
            cpa16(&Ab[r * 40 + c * 4], &A[(size_t)(m0 + r) * 1024 + k0 + c * 4]);
        }
        #pragma unroll
        for (int j = 0; j < 2; j++) {          // Wt: 128 rows (n) x 32 floats
            int id = j * 512 + tid;
            int r = id >> 3, c = id & 7;
            cpa16(&Wb[r * 40 + c * 4], &W[(size_t)(n0 + r) * 1024 + k0 + c * 4]);
        }
    };

    ISSUE(0); asm volatile("cp.async.commit_group;\n");
    ISSUE(1); asm volatile("cp.async.commit_group;\n");

    for (int it = 0; it < 32; it++) {
        asm volatile("cp.async.wait_group 1;\n");  // stage `it` ready (2-iter cover)
        __syncthreads();                           // all copies visible; compute(it-1) done
        if (it + 2 < 32) ISSUE(it + 2);            // WAR-safe: buffer (it-1)%3
        asm volatile("cp.async.commit_group;\n");  // always commit (keeps count)

        const float* Ab = Apool + (it % GSTG) * AS_ST;
        const float* Wb = Wpool + (it % GSTG) * WS_ST;
        #pragma unroll
        for (int kk = 0; kk < 32; kk += 8) {
            unsigned a[4][4], b[4][2];
            #pragma unroll
            for (int mt = 0; mt < 4; mt++) {
                int rb = wm * 64 + mt * 16;
                float2 lo = *(const float2*)&Ab[(rb + g    ) * 40 + kk + 2 * tg];
                float2 hi = *(const float2*)&Ab[(rb + g + 8) * 40 + kk + 2 * tg];
                a[mt][0] = f2u(lo.x); a[mt][1] = f2u(hi.x);
                a[mt][2] = f2u(lo.y); a[mt][3] = f2u(hi.y);
            }
            #pragma unroll
            for (int nt = 0; nt < 4; nt++) {
                int nb = wn * 32 + nt * 8;
                float2 bp = *(const float2*)&Wb[(nb + g) * 40 + kk + 2 * tg];
                b[nt][0] = f2u(bp.x); b[nt][1] = f2u(bp.y);
            }
            #pragma unroll
            for (int mt = 0; mt < 4; mt++)
                #pragma unroll
                for (int nt = 0; nt < 4; nt++)
                    mma8(acc[mt][nt], a[mt], b[nt]);
        }
    }

    #pragma unroll
    for (int mt = 0; mt < 4; mt++) {
        #pragma unroll
        for (int nt = 0; nt < 4; nt++) {
            int colL = wn * 32 + nt * 8 + 2 * tg;
            int rA = m0 + wm * 64 + mt * 16 + g;
            int rB = rA + 8;
            float c0 = acc[mt][nt][0], c1 = acc[mt][nt][1];
            float c2 = acc[mt][nt][2], c3 = acc[mt][nt][3];
            if (mode == 0) {
                float b0 = bias[n0 + colL], b1 = bias[n0 + colL + 1];
                *(float2*)&C[(size_t)rA * 1024 + n0 + colL] = make_float2(c0 + b0, c1 + b1);
                *(float2*)&C[(size_t)rB * 1024 + n0 + colL] = make_float2(c2 + b0, c3 + b1);
            } else {
                int gc = n0 + colL;
                int h = gc >> 6, d = gc & 63;
                int bA = rA >> 11, tA = rA & 2047;
                int bB = rB >> 11, tB = rB & 2047;
                if (blockIdx.z == 2) {
                    // V: write transposed + key-permuted into g_vt
                    size_t baseA = ((size_t)(bA * Hh + h) * HDIM + d) * Tt;
                    size_t baseB = ((size_t)(bB * Hh + h) * HDIM + d) * Tt;
                    int tpA = kpos(tA), tpB = kpos(tB);
                    C[baseA      + tpA] = rtf(c0);
                    C[baseA + Tt + tpA] = rtf(c1);
                    C[baseB      + tpB] = rtf(c2);
                    C[baseB + Tt + tpB] = rtf(c3);
                } else {
                    // Q,K: head-split, d-permuted
                    float* dA = &C[((size_t)(bA * Hh + h) * Tt + tA) * HDIM];
                    float* dB = &C[((size_t)(bB * Hh + h) * Tt + tB) * HDIM];
                    int p0 = kpos(d), p1 = kpos(d + 1);
                    dA[p0] = rtf(c0); dA[p1] = rtf(c1);
                    dB[p0] = rtf(c2); dB[p1] = rtf(c3);
                }
            }
        }
    }
}

// ---------------------------------------------------------------------------
// Flash attention (tf32 mma.sync), PERSISTENT — unchanged from R13.
// ---------------------------------------------------------------------------
#define FSMEM ((128*72 + 2*64*72 + 2*64*72) * 4)   // 110592

__global__ __launch_bounds__(256, 2)
void flash_mma(const float* __restrict__ q, const float* __restrict__ k,
               const float* __restrict__ vt, float* __restrict__ ctx)
{
    extern __shared__ float sm[];
    float* Qs  = sm;                       // [128][72]
    float* Ks  = sm + 128 * 72;            // [2][64][72]
    float* Vtb = Ks + 2 * 64 * 72;         // [2][64][72]
    __shared__ int s_item;

    const int tid  = threadIdx.x;
    const int lane = tid & 31, warp = tid >> 5;
    const int g = lane >> 2, tg = lane & 3;
    const int wq = warp * 16;
    const float QSC = 0.18033688011112042f;   // (1/sqrt(64))*log2(e)

    for (;;) {
        if (tid == 0) s_item = atomicAdd(&g_ctr, 1);
        __syncthreads();
        const int item = s_item;
        if (item >= NITEMS) break;

        const int qt = 15 - (item >> 5);      // heaviest first
        const int bh = item & 31;
        const int h = bh & 15, b = bh >> 4;
        const int q0 = qt * 128;

        const size_t bho = (size_t)(b * Hh + h) * (Tt * HDIM);
        const float* qb = q + bho;
        const float* kb = k + bho;
        const float* vp = vt + bho;           // [d][tperm], d-major

        #pragma unroll
        for (int i = 0; i < 8; i++) {
            int idx = i * 256 + tid;
            int r = idx >> 4, c4 = (idx & 15) * 4;
            float4 x = *(const float4*)&qb[(size_t)(q0 + r) * HDIM + c4];
            *(float4*)&Qs[r * 72 + c4] = make_float4(rtf(x.x * QSC), rtf(x.y * QSC),
                                                     rtf(x.z * QSC), rtf(x.w * QSC));
        }

        auto ISSKV = [&](int kt, int s) {
            const int k0 = kt * 64;
            #pragma unroll
            for (int i = 0; i < 4; i++) {
                int id = i * 256 + tid;
                int r = id >> 4, c4 = (id & 15) * 4;
                cpa16(&Ks [s * (64*72) + r * 72 + c4], &kb[(size_t)(k0 + r) * HDIM + c4]);
                cpa16(&Vtb[s * (64*72) + r * 72 + c4], &vp[(size_t)r * Tt + k0 + c4]);
            }
        };

        float mrow[2] = {-1e30f, -1e30f};
        float lrow[2] = {0.f, 0.f};
        float O[8][4];
        #pragma unroll
        for (int nt = 0; nt < 8; nt++)
            #pragma unroll
            for (int j = 0; j < 4; j++) O[nt][j] = 0.f;

        const int ktmax = 2 * qt + 1;
        ISSKV(0, 0); asm volatile("cp.async.commit_group;\n");

        for (int kt = 0; kt <= ktmax; kt++) {
            const int s = kt & 1;
            const int k0 = kt * 64;
            asm volatile("cp.async.wait_group 0;\n");
            __syncthreads();
            if (kt < ktmax) {
                ISSKV(kt + 1, s ^ 1);
                asm volatile("cp.async.commit_group;\n");
            }

            if (k0 <= q0 + wq + 15) {
                const float* Kb = Ks  + s * (64*72);
                const float* Vb = Vtb + s * (64*72);

                float S[8][4];
                #pragma unroll
                for (int nt = 0; nt < 8; nt++)
                    #pragma unroll
                    for (int j = 0; j < 4; j++) S[nt][j] = 0.f;

                #pragma unroll
                for (int kk = 0; kk < 64; kk += 8) {
                    float2 qlo = *(const float2*)&Qs[(wq + g    ) * 72 + kk + 2 * tg];
                    float2 qhi = *(const float2*)&Qs[(wq + g + 8) * 72 + kk + 2 * tg];
                    unsigned a[4] = { f2u(qlo.x), f2u(qhi.x), f2u(qlo.y), f2u(qhi.y) };
                    #pragma unroll
                    for (int nt = 0; nt < 8; nt++) {
                        float2 kp = *(const float2*)&Kb[(nt * 8 + g) * 72 + kk + 2 * tg];
                        unsigned bv[2] = { f2u(kp.x), f2u(kp.y) };
                        mma8(S[nt], a, bv);
                    }
                }

                if (k0 + 63 > q0 + wq) {
                    int qA = q0 + wq + g, qB = qA + 8;
                    #pragma unroll
                    for (int nt = 0; nt < 8; nt++) {
                        int c = k0 + nt * 8 + 2 * tg;
                        if (c     > qA) S[nt][0] = -1e30f;
                        if (c + 1 > qA) S[nt][1] = -1e30f;
                        if (c     > qB) S[nt][2] = -1e30f;
                        if (c + 1 > qB) S[nt][3] = -1e30f;
                    }
                }

                float mA = -1e30f, mB = -1e30f;
                #pragma unroll
                for (int nt = 0; nt < 8; nt++) {
                    mA = fmaxf(mA, fmaxf(S[nt][0], S[nt][1]));
                    mB = fmaxf(mB, fmaxf(S[nt][2], S[nt][3]));
                }
                #pragma unroll
                for (int o = 1; o <= 2; o <<= 1) {
                    mA = fmaxf(mA, __shfl_xor_sync(0xffffffffu, mA, o));
                    mB = fmaxf(mB, __shfl_xor_sync(0xffffffffu, mB, o));
                }
                float nmA = fmaxf(mrow[0], mA), nmB = fmaxf(mrow[1], mB);
                float sA = 0.f, sB = 0.f;
                #pragma unroll
                for (int nt = 0; nt < 8; nt++) {
                    S[nt][0] = ex2(S[nt][0] - nmA);
                    S[nt][1] = ex2(S[nt][1] - nmA);
                    S[nt][2] = ex2(S[nt][2] - nmB);
                    S[nt][3] = ex2(S[nt][3] - nmB);
                    sA += S[nt][0] + S[nt][1];
                    sB += S[nt][2] + S[nt][3];
                }
                #pragma unroll
                for (int o = 1; o <= 2; o <<= 1) {
                    sA += __shfl_xor_sync(0xffffffffu, sA, o);
                    sB += __shfl_xor_sync(0xffffffffu, sB, o);
                }
                float scA = ex2(mrow[0] - nmA), scB = ex2(mrow[1] - nmB);
                lrow[0] = lrow[0] * scA + sA;  mrow[0] = nmA;
                lrow[1] = lrow[1] * scB + sB;  mrow[1] = nmB;
                #pragma unroll
                for (int nt = 0; nt < 8; nt++) {
                    O[nt][0] *= scA; O[nt][1] *= scA;
                    O[nt][2] *= scB; O[nt][3] *= scB;
                }

                const int src0 = (lane & ~3) | (tg >> 1);
                const int src1 = src0 + 2;
                const bool odd = tg & 1;
                #pragma unroll
                for (int j = 0; j < 8; j++) {
                    float v00 = __shfl_sync(0xffffffffu, S[j][0], src0);
                    float v01 = __shfl_sync(0xffffffffu, S[j][1], src0);
                    float v02 = __shfl_sync(0xffffffffu, S[j][2], src0);
                    float v03 = __shfl_sync(0xffffffffu, S[j][3], src0);
                    float v10 = __shfl_sync(0xffffffffu, S[j][0], src1);
                    float v11 = __shfl_sync(0xffffffffu, S[j][1], src1);
                    float v12 = __shfl_sync(0xffffffffu, S[j][2], src1);
                    float v13 = __shfl_sync(0xffffffffu, S[j][3], src1);
                    unsigned a[4];
                    a[0] = rtf_u(odd ? v01 : v00);
                    a[1] = rtf_u(odd ? v03 : v02);
                    a[2] = rtf_u(odd ? v11 : v10);
                    a[3] = rtf_u(odd ? v13 : v12);
                    #pragma unroll
                    for (int nt = 0; nt < 8; nt++) {
                        float2 vv = *(const float2*)&Vb[(nt * 8 + g) * 72 + 8 * j + 2 * tg];
                        unsigned bv[2] = { f2u(vv.x), f2u(vv.y) };
                        mma8(O[nt], a, bv);
                    }
                }
            }
        }

        float invA = 1.0f / lrow[0], invB = 1.0f / lrow[1];
        int tA = q0 + wq + g, tB = tA + 8;
        float* rowA = &ctx[((size_t)b * Tt + tA) * Dd];
        float* rowB = &ctx[((size_t)b * Tt + tB) * Dd];
        #pragma unroll
        for (int nt = 0; nt < 8; nt++) {
            int c = h * HDIM + nt * 8 + 2 * tg;
            int p0 = kpos(c), p1 = kpos(c + 1);
            rowA[p0] = rtf(O[nt][0] * invA);
            rowA[p1] = rtf(O[nt][1] * invA);
            rowB[p0] = rtf(O[nt][2] * invB);
            rowB[p1] = rtf(O[nt][3] * invB);
        }
    }
}

// ---------------------------------------------------------------------------
extern "C" void kernel_launch(void* const* d_in, const int* in_sizes, int n_in,
                              void* d_out, int out_size)
{
    const float* x  = (const float*)d_in[0];
    const float* Wq = (const float*)d_in[1];
    const float* Wk = (const float*)d_in[2];
    const float* Wv = (const float*)d_in[3];
    const float* Wo = (const float*)d_in[4];
    const float* bo = (const float*)d_in[5];
    float* out = (float*)d_out;

    float *pq, *pk, *pvt, *pctx, *pxr, *pwt;
    cudaGetSymbolAddress((void**)&pq,   g_q);
    cudaGetSymbolAddress((void**)&pk,   g_k);
    cudaGetSymbolAddress((void**)&pvt,  g_vt);
    cudaGetSymbolAddress((void**)&pctx, g_ctx);
    cudaGetSymbolAddress((void**)&pxr,  g_xr);
    cudaGetSymbolAddress((void**)&pwt,  g_wt);
    float* wt0 = pwt;
    float* wt1 = pwt + (size_t)Dd*Dd;
    float* wt2 = pwt + 2*(size_t)Dd*Dd;
    float* wt3 = pwt + 3*(size_t)Dd*Dd;

    cudaFuncSetAttribute(gemm_mma,  cudaFuncAttributeMaxDynamicSharedMemorySize, GSMEM);
    cudaFuncSetAttribute(flash_mma, cudaFuncAttributeMaxDynamicSharedMemorySize, FSMEM);

    preround_x<<<4096, 256>>>(x);
    transW<<<dim3(32, 32, 4), dim3(32, 8)>>>(Wq, Wk, Wv, Wo);

    gemm_mma<<<dim3(Dd/128, MTOT/256, 3), 512, GSMEM>>>(
        pxr, wt0, wt1, wt2, pq, pk, pvt, nullptr, 1);

    flash_mma<<<304, 256, FSMEM>>>(pq, pk, pvt, pctx);

    gemm_mma<<<dim3(Dd/128, MTOT/256, 1), 512, GSMEM>>>(
        pctx, wt3, nullptr, nullptr, out, nullptr, nullptr, bo, 0);
}

// round 15
// speedup vs baseline: 1.5460x; 1.5460x over previous
#include <cuda_runtime.h>
#include <cstdint>

#define Bb   2
#define Tt   2048
#define Dd   1024
#define Hh   16
#define HDIM 64
#define MTOT (Bb*Tt)        // 4096
#define NITEMS 512          // flash work items (16 qt x 16 h x 2 b)

// Scratch (allocation-free rule: __device__ globals)
__device__ float g_q[Bb*Hh*Tt*HDIM];     // d-dim permuted
__device__ float g_k[Bb*Hh*Tt*HDIM];     // d-dim permuted
__device__ float g_vt[Bb*Hh*HDIM*Tt];    // transposed V [b][h][d][tperm]
__device__ float g_ctx[Bb*Tt*Dd];        // d-dim permuted (A of Wo gemm)
__device__ float g_xr[MTOT*Dd];          // tf32-rounded x, k-perm
__device__ float g_wt[4][Dd*Dd];         // tf32-rounded W^T [n][k], k-perm
__device__ int   g_ctr;                  // flash work counter

// ---- helpers --------------------------------------------------------------
__device__ __forceinline__ unsigned rtf_u(float x) {
    unsigned u; asm("cvt.rna.tf32.f32 %0, %1;" : "=r"(u) : "f"(x)); return u;
}
__device__ __forceinline__ float rtf(float x) { return __uint_as_float(rtf_u(x)); }
__device__ __forceinline__ unsigned f2u(float x) { return __float_as_uint(x); }
__device__ __forceinline__ void cpa16(void* dst, const void* src) {
    unsigned s = (unsigned)__cvta_generic_to_shared(dst);
    asm volatile("cp.async.cg.shared.global [%0], [%1], 16;\n" :: "r"(s), "l"(src));
}
__device__ __forceinline__ float ex2(float x) {
    float y; asm("ex2.approx.ftz.f32 %0, %1;" : "=f"(y) : "f"(x)); return y;
}
// position p holds original k-offset (p>>1)+4*(p&1)  (within each 8-block)
__device__ __forceinline__ int korig(int p) {
    return (p & ~7) + (((p & 7) >> 1)) + 4 * (p & 1);
}
// original offset c stored at position 2*(c&3)+((c>>2)&1)
__device__ __forceinline__ int kpos(int c) {
    return (c & ~7) + 2 * (c & 3) + ((c >> 2) & 1);
}
// mma.sync m16n8k8 tf32: D += A*B
__device__ __forceinline__ void mma8(float* d, const unsigned* a, const unsigned* b) {
    asm volatile(
        "mma.sync.aligned.m16n8k8.row.col.f32.tf32.tf32.f32 "
        "{%0,%1,%2,%3}, {%4,%5,%6,%7}, {%8,%9}, {%0,%1,%2,%3};\n"
        : "+f"(d[0]), "+f"(d[1]), "+f"(d[2]), "+f"(d[3])
        : "r"(a[0]), "r"(a[1]), "r"(a[2]), "r"(a[3]), "r"(b[0]), "r"(b[1]));
}

// ---------------------------------------------------------------------------
// prep: grid (32, 32, 5), block 256.
//   z in 0..3 : g_wt[z][n][p] = rtf(W_z[k0+korig(p)][n])  (transpose + k-perm)
//   z == 4    : g_xr[m][p] = rtf(x[m][korig(p)])  (1024 blocks x 4 chunks)
//               + resets flash work counter.
// ---------------------------------------------------------------------------
__global__ void prep(const float* __restrict__ x,
                     const float* __restrict__ wq, const float* __restrict__ wk,
                     const float* __restrict__ wv, const float* __restrict__ wo)
{
    __shared__ float t[32][33];
    const int z = blockIdx.z;
    if (z < 4) {
        const float* W = (z == 0) ? wq : (z == 1) ? wk : (z == 2) ? wv : wo;
        float* D = g_wt[z];
        int k0 = blockIdx.x * 32, n0 = blockIdx.y * 32;
        int tx = threadIdx.x & 31, ty = threadIdx.x >> 5;   // (32,8)
        #pragma unroll
        for (int i = 0; i < 32; i += 8)
            t[ty + i][tx] = rtf(W[(size_t)(k0 + ty + i) * 1024 + n0 + tx]);
        __syncthreads();
        int src = korig(tx);
        #pragma unroll
        for (int i = 0; i < 32; i += 8)
            D[(size_t)(n0 + ty + i) * 1024 + k0 + tx] = t[src][ty + i];
    } else {
        int bid = blockIdx.y * 32 + blockIdx.x;             // 0..1023
        if (bid == 0 && threadIdx.x == 0) g_ctr = 0;
        #pragma unroll
        for (int c = 0; c < 4; c++) {
            int i = ((bid * 4 + c) * 256 + threadIdx.x) * 4;
            int m = i >> 10, kp = i & 1023;
            const float* row = x + (size_t)m * 1024;
            float4 o;
            o.x = rtf(row[korig(kp)]);
            o.y = rtf(row[korig(kp + 1)]);
            o.z = rtf(row[korig(kp + 2)]);
            o.w = rtf(row[korig(kp + 3)]);
            *(float4*)&g_xr[i] = o;
        }
    }
}

// ---------------------------------------------------------------------------
// GEMM (tf32 mma.sync, float2 fragment loads, 2-stage cp.async) — R13 config:
// 256 threads, 128x128 tile, 2 CTAs/SM (inter-CTA overlap covers latency).
// mode 0: row-major + bias.
// mode 1: z∈{0,1} -> Q/K head-split d-permuted; z==2 -> V transposed+key-perm.
// ---------------------------------------------------------------------------
#define AS_ST (128*40)
#define WS_ST (128*40)
#define GSTG  2
#define GSMEM (GSTG * (AS_ST + WS_ST) * 4)     // 81920 B

__global__ __launch_bounds__(256, 2)
void gemm_mma(const float* __restrict__ A,
              const float* __restrict__ W0, const float* __restrict__ W1,
              const float* __restrict__ W2,
              float* __restrict__ C0, float* __restrict__ C1,
              float* __restrict__ C2,
              const float* __restrict__ bias, int mode)
{
    extern __shared__ float sh[];
    float* Apool = sh;                  // [2][128][40]
    float* Wpool = sh + GSTG * AS_ST;   // [2][128][40]  ([n][k] layout)

    const float* W = (blockIdx.z == 0) ? W0 : (blockIdx.z == 1) ? W1 : W2;
    float*       C = (blockIdx.z == 0) ? C0 : (blockIdx.z == 1) ? C1 : C2;

    const int tid = threadIdx.x;
    const int lane = tid & 31, warp = tid >> 5;
    const int g = lane >> 2, tg = lane & 3;
    const int wm = warp >> 2;
    const int wn = warp & 3;
    const int m0 = blockIdx.y * 128;
    const int n0 = blockIdx.x * 128;

    float acc[4][4][4];
    #pragma unroll
    for (int mt = 0; mt < 4; mt++)
        #pragma unroll
        for (int nt = 0; nt < 4; nt++)
            #pragma unroll
            for (int c = 0; c < 4; c++) acc[mt][nt][c] = 0.f;

    auto ISSUE = [&](int it) {
        const int k0 = it * 32;
        float* Ab = Apool + (it & 1) * AS_ST;
        float* Wb = Wpool + (it & 1) * WS_ST;
        #pragma unroll
        for (int j = 0; j < 4; j++) {
            int id = j * 256 + tid;
            int r = id >> 3, c = id & 7;
            cpa16(&Ab[r * 40 + c * 4], &A[(size_t)(m0 + r) * 1024 + k0 + c * 4]);
        }
        #pragma unroll
        for (int j = 0; j < 4; j++) {
            int id = j * 256 + tid;
            int r = id >> 3, c = id & 7;
            cpa16(&Wb[r * 40 + c * 4], &W[(size_t)(n0 + r) * 1024 + k0 + c * 4]);
        }
    };

    ISSUE(0); asm volatile("cp.async.commit_group;\n");

    for (int it = 0; it < 32; it++) {
        asm volatile("cp.async.wait_group 0;\n");
        __syncthreads();
        if (it + 1 < 32) {
            ISSUE(it + 1);
            asm volatile("cp.async.commit_group;\n");
        }

        const float* Ab = Apool + (it & 1) * AS_ST;
        const float* Wb = Wpool + (it & 1) * WS_ST;
        #pragma unroll
        for (int kk = 0; kk < 32; kk += 8) {
            unsigned a[4][4], b[4][2];
            #pragma unroll
            for (int mt = 0; mt < 4; mt++) {
                int rb = wm * 64 + mt * 16;
                float2 lo = *(const float2*)&Ab[(rb + g    ) * 40 + kk + 2 * tg];
                float2 hi = *(const float2*)&Ab[(rb + g + 8) * 40 + kk + 2 * tg];
                a[mt][0] = f2u(lo.x); a[mt][1] = f2u(hi.x);
                a[mt][2] = f2u(lo.y); a[mt][3] = f2u(hi.y);
            }
            #pragma unroll
            for (int nt = 0; nt < 4; nt++) {
                int nb = wn * 32 + nt * 8;
                float2 bp = *(const float2*)&Wb[(nb + g) * 40 + kk + 2 * tg];
                b[nt][0] = f2u(bp.x); b[nt][1] = f2u(bp.y);
            }
            #pragma unroll
            for (int mt = 0; mt < 4; mt++)
                #pragma unroll
                for (int nt = 0; nt < 4; nt++)
                    mma8(acc[mt][nt], a[mt], b[nt]);
        }
    }

    #pragma unroll
    for (int mt = 0; mt < 4; mt++) {
        #pragma unroll
        for (int nt = 0; nt < 4; nt++) {
            int colL = wn * 32 + nt * 8 + 2 * tg;
            int rA = m0 + wm * 64 + mt * 16 + g;
            int rB = rA + 8;
            float c0 = acc[mt][nt][0], c1 = acc[mt][nt][1];
            float c2 = acc[mt][nt][2], c3 = acc[mt][nt][3];
            if (mode == 0) {
                float b0 = bias[n0 + colL], b1 = bias[n0 + colL + 1];
                *(float2*)&C[(size_t)rA * 1024 + n0 + colL] = make_float2(c0 + b0, c1 + b1);
                *(float2*)&C[(size_t)rB * 1024 + n0 + colL] = make_float2(c2 + b0, c3 + b1);
            } else {
                int gc = n0 + colL;
                int h = gc >> 6, d = gc & 63;
                int bA = rA >> 11, tA = rA & 2047;
                int bB = rB >> 11, tB = rB & 2047;
                if (blockIdx.z == 2) {
                    // V: write transposed + key-permuted into g_vt
                    size_t baseA = ((size_t)(bA * Hh + h) * HDIM + d) * Tt;
                    size_t baseB = ((size_t)(bB * Hh + h) * HDIM + d) * Tt;
                    int tpA = kpos(tA), tpB = kpos(tB);
                    C[baseA      + tpA] = rtf(c0);
                    C[baseA + Tt + tpA] = rtf(c1);
                    C[baseB      + tpB] = rtf(c2);
                    C[baseB + Tt + tpB] = rtf(c3);
                } else {
                    // Q,K: head-split, d-permuted
                    float* dA = &C[((size_t)(bA * Hh + h) * Tt + tA) * HDIM];
                    float* dB = &C[((size_t)(bB * Hh + h) * Tt + tB) * HDIM];
                    int p0 = kpos(d), p1 = kpos(d + 1);
                    dA[p0] = rtf(c0); dA[p1] = rtf(c1);
                    dB[p0] = rtf(c2); dB[p1] = rtf(c3);
                }
            }
        }
    }
}

// ---------------------------------------------------------------------------
// Flash attention (tf32 mma.sync), PERSISTENT — unchanged from R13.
// ---------------------------------------------------------------------------
#define FSMEM ((128*72 + 2*64*72 + 2*64*72) * 4)   // 110592

__global__ __launch_bounds__(256, 2)
void flash_mma(const float* __restrict__ q, const float* __restrict__ k,
               const float* __restrict__ vt, float* __restrict__ ctx)
{
    extern __shared__ float sm[];
    float* Qs  = sm;                       // [128][72]
    float* Ks  = sm + 128 * 72;            // [2][64][72]
    float* Vtb = Ks + 2 * 64 * 72;         // [2][64][72]
    __shared__ int s_item;

    const int tid  = threadIdx.x;
    const int lane = tid & 31, warp = tid >> 5;
    const int g = lane >> 2, tg = lane & 3;
    const int wq = warp * 16;
    const float QSC = 0.18033688011112042f;   // (1/sqrt(64))*log2(e)

    for (;;) {
        if (tid == 0) s_item = atomicAdd(&g_ctr, 1);
        __syncthreads();
        const int item = s_item;
        if (item >= NITEMS) break;

        const int qt = 15 - (item >> 5);      // heaviest first
        const int bh = item & 31;
        const int h = bh & 15, b = bh >> 4;
        const int q0 = qt * 128;

        const size_t bho = (size_t)(b * Hh + h) * (Tt * HDIM);
        const float* qb = q + bho;
        const float* kb = k + bho;
        const float* vp = vt + bho;           // [d][tperm], d-major

        #pragma unroll
        for (int i = 0; i < 8; i++) {
            int idx = i * 256 + tid;
            int r = idx >> 4, c4 = (idx & 15) * 4;
            float4 x = *(const float4*)&qb[(size_t)(q0 + r) * HDIM + c4];
            *(float4*)&Qs[r * 72 + c4] = make_float4(rtf(x.x * QSC), rtf(x.y * QSC),
                                                     rtf(x.z * QSC), rtf(x.w * QSC));
        }

        auto ISSKV = [&](int kt, int s) {
            const int k0 = kt * 64;
            #pragma unroll
            for (int i = 0; i < 4; i++) {
                int id = i * 256 + tid;
                int r = id >> 4, c4 = (id & 15) * 4;
                cpa16(&Ks [s * (64*72) + r * 72 + c4], &kb[(size_t)(k0 + r) * HDIM + c4]);
                cpa16(&Vtb[s * (64*72) + r * 72 + c4], &vp[(size_t)r * Tt + k0 + c4]);
            }
        };

        float mrow[2] = {-1e30f, -1e30f};
        float lrow[2] = {0.f, 0.f};
        float O[8][4];
        #pragma unroll
        for (int nt = 0; nt < 8; nt++)
            #pragma unroll
            for (int j = 0; j < 4; j++) O[nt][j] = 0.f;

        const int ktmax = 2 * qt + 1;
        ISSKV(0, 0); asm volatile("cp.async.commit_group;\n");

        for (int kt = 0; kt <= ktmax; kt++) {
            const int s = kt & 1;
            const int k0 = kt * 64;
            asm volatile("cp.async.wait_group 0;\n");
            __syncthreads();
            if (kt < ktmax) {
                ISSKV(kt + 1, s ^ 1);
                asm volatile("cp.async.commit_group;\n");
            }

            if (k0 <= q0 + wq + 15) {
                const float* Kb = Ks  + s * (64*72);
                const float* Vb = Vtb + s * (64*72);

                float S[8][4];
                #pragma unroll
                for (int nt = 0; nt < 8; nt++)
                    #pragma unroll
                    for (int j = 0; j < 4; j++) S[nt][j] = 0.f;

                #pragma unroll
                for (int kk = 0; kk < 64; kk += 8) {
                    float2 qlo = *(const float2*)&Qs[(wq + g    ) * 72 + kk + 2 * tg];
                    float2 qhi = *(const float2*)&Qs[(wq + g + 8) * 72 + kk + 2 * tg];
                    unsigned a[4] = { f2u(qlo.x), f2u(qhi.x), f2u(qlo.y), f2u(qhi.y) };
                    #pragma unroll
                    for (int nt = 0; nt < 8; nt++) {
                        float2 kp = *(const float2*)&Kb[(nt * 8 + g) * 72 + kk + 2 * tg];
                        unsigned bv[2] = { f2u(kp.x), f2u(kp.y) };
                        mma8(S[nt], a, bv);
                    }
                }

                if (k0 + 63 > q0 + wq) {
                    int qA = q0 + wq + g, qB = qA + 8;
                    #pragma unroll
                    for (int nt = 0; nt < 8; nt++) {
                        int c = k0 + nt * 8 + 2 * tg;
                        if (c     > qA) S[nt][0] = -1e30f;
                        if (c + 1 > qA) S[nt][1] = -1e30f;
                        if (c     > qB) S[nt][2] = -1e30f;
                        if (c + 1 > qB) S[nt][3] = -1e30f;
                    }
                }

                float mA = -1e30f, mB = -1e30f;
                #pragma unroll
                for (int nt = 0; nt < 8; nt++) {
                    mA = fmaxf(mA, fmaxf(S[nt][0], S[nt][1]));
                    mB = fmaxf(mB, fmaxf(S[nt][2], S[nt][3]));
                }
                #pragma unroll
                for (int o = 1; o <= 2; o <<= 1) {
                    mA = fmaxf(mA, __shfl_xor_sync(0xffffffffu, mA, o));
                    mB = fmaxf(mB, __shfl_xor_sync(0xffffffffu, mB, o));
                }
                float nmA = fmaxf(mrow[0], mA), nmB = fmaxf(mrow[1], mB);
                float sA = 0.f, sB = 0.f;
                #pragma unroll
                for (int nt = 0; nt < 8; nt++) {
                    S[nt][0] = ex2(S[nt][0] - nmA);
                    S[nt][1] = ex2(S[nt][1] - nmA);
                    S[nt][2] = ex2(S[nt][2] - nmB);
                    S[nt][3] = ex2(S[nt][3] - nmB);
                    sA += S[nt][0] + S[nt][1];
                    sB += S[nt][2] + S[nt][3];
                }
                #pragma unroll
                for (int o = 1; o <= 2; o <<= 1) {
                    sA += __shfl_xor_sync(0xffffffffu, sA, o);
                    sB += __shfl_xor_sync(0xffffffffu, sB, o);
                }
                float scA = ex2(mrow[0] - nmA), scB = ex2(mrow[1] - nmB);
                lrow[0] = lrow[0] * scA + sA;  mrow[0] = nmA;
                lrow[1] = lrow[1] * scB + sB;  mrow[1] = nmB;
                #pragma unroll
                for (int nt = 0; nt < 8; nt++) {
                    O[nt][0] *= scA; O[nt][1] *= scA;
                    O[nt][2] *= scB; O[nt][3] *= scB;
                }

                const int src0 = (lane & ~3) | (tg >> 1);
                const int src1 = src0 + 2;
                const bool odd = tg & 1;
                #pragma unroll
                for (int j = 0; j < 8; j++) {
                    float v00 = __shfl_sync(0xffffffffu, S[j][0], src0);
                    float v01 = __shfl_sync(0xffffffffu, S[j][1], src0);
                    float v02 = __shfl_sync(0xffffffffu, S[j][2], src0);
                    float v03 = __shfl_sync(0xffffffffu, S[j][3], src0);
                    float v10 = __shfl_sync(0xffffffffu, S[j][0], src1);
                    float v11 = __shfl_sync(0xffffffffu, S[j][1], src1);
                    float v12 = __shfl_sync(0xffffffffu, S[j][2], src1);
                    float v13 = __shfl_sync(0xffffffffu, S[j][3], src1);
                    unsigned a[4];
                    a[0] = rtf_u(odd ? v01 : v00);
                    a[1] = rtf_u(odd ? v03 : v02);
                    a[2] = rtf_u(odd ? v11 : v10);
                    a[3] = rtf_u(odd ? v13 : v12);
                    #pragma unroll
                    for (int nt = 0; nt < 8; nt++) {
                        float2 vv = *(const float2*)&Vb[(nt * 8 + g) * 72 + 8 * j + 2 * tg];
                        unsigned bv[2] = { f2u(vv.x), f2u(vv.y) };
                        mma8(O[nt], a, bv);
                    }
                }
            }
        }

        float invA = 1.0f / lrow[0], invB = 1.0f / lrow[1];
        int tA = q0 + wq + g, tB = tA + 8;
        float* rowA = &ctx[((size_t)b * Tt + tA) * Dd];
        float* rowB = &ctx[((size_t)b * Tt + tB) * Dd];
        #pragma unroll
        for (int nt = 0; nt < 8; nt++) {
            int c = h * HDIM + nt * 8 + 2 * tg;
            int p0 = kpos(c), p1 = kpos(c + 1);
            rowA[p0] = rtf(O[nt][0] * invA);
            rowA[p1] = rtf(O[nt][1] * invA);
            rowB[p0] = rtf(O[nt][2] * invB);
            rowB[p1] = rtf(O[nt][3] * invB);
        }
    }
}

// ---------------------------------------------------------------------------
extern "C" void kernel_launch(void* const* d_in, const int* in_sizes, int n_in,
                              void* d_out, int out_size)
{
    const float* x  = (const float*)d_in[0];
    const float* Wq = (const float*)d_in[1];
    const float* Wk = (const float*)d_in[2];
    const float* Wv = (const float*)d_in[3];
    const float* Wo = (const float*)d_in[4];
    const float* bo = (const float*)d_in[5];
    float* out = (float*)d_out;

    float *pq, *pk, *pvt, *pctx, *pxr, *pwt;
    cudaGetSymbolAddress((void**)&pq,   g_q);
    cudaGetSymbolAddress((void**)&pk,   g_k);
    cudaGetSymbolAddress((void**)&pvt,  g_vt);
    cudaGetSymbolAddress((void**)&pctx, g_ctx);
    cudaGetSymbolAddress((void**)&pxr,  g_xr);
    cudaGetSymbolAddress((void**)&pwt,  g_wt);
    float* wt0 = pwt;
    float* wt1 = pwt + (size_t)Dd*Dd;
    float* wt2 = pwt + 2*(size_t)Dd*Dd;
    float* wt3 = pwt + 3*(size_t)Dd*Dd;

    cudaFuncSetAttribute(gemm_mma,  cudaFuncAttributeMaxDynamicSharedMemorySize, GSMEM);
    cudaFuncSetAttribute(flash_mma, cudaFuncAttributeMaxDynamicSharedMemorySize, FSMEM);

    prep<<<dim3(32, 32, 5), 256>>>(x, Wq, Wk, Wv, Wo);

    gemm_mma<<<dim3(Dd/128, MTOT/128, 3), 256, GSMEM>>>(
        pxr, wt0, wt1, wt2, pq, pk, pvt, nullptr, 1);

    flash_mma<<<304, 256, FSMEM>>>(pq, pk, pvt, pctx);

    gemm_mma<<<dim3(Dd/128, MTOT/128, 1), 256, GSMEM>>>(
        pctx, wt3, nullptr, nullptr, out, nullptr, nullptr, bo, 0);
}